// round 1
// baseline (speedup 1.0000x reference)
#include <cuda_runtime.h>
#include <math.h>

// Problem constants (fixed by setup_inputs)
#define B_    2
#define L_    2048
#define E_    1024
#define H_    16
#define HD_   64
#define KD_   1024     // input_dim
#define NQKV_ 3072
#define ML_   (B_*L_)  // 4096 rows

// Attention tiling
#define QT_   64        // queries per block
#define SPAN_ 128       // K/V rows staged per tile (QT_ + 64)
#define WPAD_ 65        // padded row stride (conflict-free: 65 % 32 == 1)

// Scratch (device globals: allocation-guard-safe)
__device__ float g_qkv[(size_t)ML_ * NQKV_];   // [B*L, 3072] : per head h: [q|k|v] at h*192
__device__ float g_att[(size_t)ML_ * E_];      // attention output [B*L, 1024]

// ---------------------------------------------------------------------------
// SGEMM: C[M,N] = A[M,K] * W[N,K]^T + bias[N]
// BM=BN=128, BK=16, 256 threads, 8x8 per thread, float4 I/O, padded smem.
// Requires M%128==0, N%128==0, K%16==0 (true for all uses here).
// ---------------------------------------------------------------------------
__global__ __launch_bounds__(256) void sgemm_nt(
    const float* __restrict__ A, const float* __restrict__ W,
    const float* __restrict__ bias, float* __restrict__ C,
    int M, int N, int K)
{
    __shared__ float As[16][132];
    __shared__ float Bs[16][132];

    const int tid = threadIdx.x;
    const int bm  = blockIdx.y * 128;
    const int bn  = blockIdx.x * 128;
    const int tm  = (tid >> 4) * 8;
    const int tn  = (tid & 15) * 8;

    float acc[8][8];
#pragma unroll
    for (int i = 0; i < 8; ++i)
#pragma unroll
        for (int j = 0; j < 8; ++j) acc[i][j] = 0.0f;

    for (int kt = 0; kt < K; kt += 16) {
#pragma unroll
        for (int i = 0; i < 2; ++i) {
            int idx = tid + i * 256;          // 0..511
            int row = idx >> 2;               // 0..127
            int c4  = (idx & 3) << 2;         // 0,4,8,12
            float4 av = *(const float4*)(A + (size_t)(bm + row) * K + kt + c4);
            float4 wv = *(const float4*)(W + (size_t)(bn + row) * K + kt + c4);
            As[c4 + 0][row] = av.x; As[c4 + 1][row] = av.y;
            As[c4 + 2][row] = av.z; As[c4 + 3][row] = av.w;
            Bs[c4 + 0][row] = wv.x; Bs[c4 + 1][row] = wv.y;
            Bs[c4 + 2][row] = wv.z; Bs[c4 + 3][row] = wv.w;
        }
        __syncthreads();

#pragma unroll
        for (int kk = 0; kk < 16; ++kk) {
            float a[8], b[8];
            *(float4*)&a[0] = *(const float4*)&As[kk][tm];
            *(float4*)&a[4] = *(const float4*)&As[kk][tm + 4];
            *(float4*)&b[0] = *(const float4*)&Bs[kk][tn];
            *(float4*)&b[4] = *(const float4*)&Bs[kk][tn + 4];
#pragma unroll
            for (int i = 0; i < 8; ++i)
#pragma unroll
                for (int j = 0; j < 8; ++j)
                    acc[i][j] += a[i] * b[j];
        }
        __syncthreads();
    }

#pragma unroll
    for (int i = 0; i < 8; ++i) {
#pragma unroll
        for (int j = 0; j < 8; j += 4) {
            float4 o;
            o.x = acc[i][j + 0] + bias[bn + tn + j + 0];
            o.y = acc[i][j + 1] + bias[bn + tn + j + 1];
            o.z = acc[i][j + 2] + bias[bn + tn + j + 2];
            o.w = acc[i][j + 3] + bias[bn + tn + j + 3];
            *(float4*)(C + (size_t)(bm + tm + i) * N + bn + tn + j) = o;
        }
    }
}

// ---------------------------------------------------------------------------
// Sliding-window attention.
// Grid: (L/QT_, H, B), 256 threads (8 warps). Each block handles QT_=64
// queries of one (b,h); stages K/V span of 128 positions in smem.
// Warp-per-query: lane computes scores for window offsets {lane, lane+32},
// lane 0 additionally offset 64. Softmax via warp shuffles. Output dims
// {lane, lane+32} accumulated from smem V with probs in smem.
// ---------------------------------------------------------------------------
__global__ __launch_bounds__(256) void swattn(
    const float* __restrict__ qkv, const int* __restrict__ pmask,
    float* __restrict__ att)
{
    extern __shared__ float sm[];
    float* Ks = sm;                       // SPAN_*WPAD_
    float* Vs = Ks + SPAN_ * WPAD_;       // SPAN_*WPAD_
    float* Qs = Vs + SPAN_ * WPAD_;       // 8*64
    float* Ps = Qs + 8 * 64;              // 8*72

    const int b  = blockIdx.z;
    const int h  = blockIdx.y;
    const int q0 = blockIdx.x * QT_;
    const int tid = threadIdx.x;

    // Stage K/V: positions q0-32 .. q0+95, zero-fill out-of-range.
    for (int idx = tid; idx < SPAN_ * 16; idx += 256) {
        int row = idx >> 4;
        int c4  = (idx & 15) << 2;
        int pos = q0 - 32 + row;
        float4 kv = make_float4(0.f, 0.f, 0.f, 0.f);
        float4 vv = make_float4(0.f, 0.f, 0.f, 0.f);
        if (pos >= 0 && pos < L_) {
            const float* base = qkv + (size_t)(b * L_ + pos) * NQKV_ + h * 192;
            kv = *(const float4*)(base + 64  + c4);
            vv = *(const float4*)(base + 128 + c4);
        }
        Ks[row * WPAD_ + c4 + 0] = kv.x; Ks[row * WPAD_ + c4 + 1] = kv.y;
        Ks[row * WPAD_ + c4 + 2] = kv.z; Ks[row * WPAD_ + c4 + 3] = kv.w;
        Vs[row * WPAD_ + c4 + 0] = vv.x; Vs[row * WPAD_ + c4 + 1] = vv.y;
        Vs[row * WPAD_ + c4 + 2] = vv.z; Vs[row * WPAD_ + c4 + 3] = vv.w;
    }
    __syncthreads();

    const int warp = tid >> 5;
    const int lane = tid & 31;
    const float scale = 0.125f;           // 1/sqrt(64)
    const float NEGS  = -100000.0f * 0.125f;

    for (int iter = 0; iter < QT_ / 8; ++iter) {
        int qi   = iter * 8 + warp;       // local query index 0..63
        int qpos = q0 + qi;

        // Stage this warp's query vector
        const float* qptr = qkv + (size_t)(b * L_ + qpos) * NQKV_ + h * 192;
        Qs[warp * 64 + lane]      = qptr[lane];
        Qs[warp * 64 + lane + 32] = qptr[lane + 32];
        __syncwarp();

        // Scores for window offsets wa=lane, wb=lane+32, (lane0) wc=64.
        int ja = qi + lane;               // local key row = qi + widx
        float sa = 0.f, sb = 0.f, sc = 0.f;
#pragma unroll
        for (int d = 0; d < 64; ++d) {
            float qd = Qs[warp * 64 + d];
            sa += qd * Ks[ja * WPAD_ + d];
            sb += qd * Ks[(ja + 32) * WPAD_ + d];
        }
        if (lane == 0) {
            int jc = qi + 64;
#pragma unroll
            for (int d = 0; d < 64; ++d)
                sc += Qs[warp * 64 + d] * Ks[jc * WPAD_ + d];
        }

        // Mask + scale (NEG semantics match reference: NEG then /sqrt(D))
        int pa = qpos - 32 + lane;
        int pb = pa + 32;
        int pc = qpos + 32;
        bool oka = (pa >= 0 && pa < L_) && (pmask[b * L_ + (pa < 0 ? 0 : (pa >= L_ ? L_ - 1 : pa))] != 0);
        bool okb = (pb >= 0 && pb < L_) && (pmask[b * L_ + (pb < 0 ? 0 : (pb >= L_ ? L_ - 1 : pb))] != 0);
        bool okc = (pc >= 0 && pc < L_) && (pmask[b * L_ + (pc < 0 ? 0 : (pc >= L_ ? L_ - 1 : pc))] != 0);
        sa = oka ? sa * scale : NEGS;
        sb = okb ? sb * scale : NEGS;
        sc = okc ? sc * scale : NEGS;

        // Warp softmax over 65 values (sa,sb per lane + sc on lane0)
        float m = fmaxf(sa, sb);
#pragma unroll
        for (int off = 16; off > 0; off >>= 1)
            m = fmaxf(m, __shfl_xor_sync(0xffffffffu, m, off));
        float sc0 = __shfl_sync(0xffffffffu, sc, 0);
        m = fmaxf(m, sc0);

        float ea = __expf(sa - m);
        float eb = __expf(sb - m);
        float ec0 = __expf(sc0 - m);
        float sum = ea + eb;
#pragma unroll
        for (int off = 16; off > 0; off >>= 1)
            sum += __shfl_xor_sync(0xffffffffu, sum, off);
        sum += ec0;
        float inv = 1.0f / sum;

        Ps[warp * 72 + lane]      = ea * inv;
        Ps[warp * 72 + lane + 32] = eb * inv;
        if (lane == 0) Ps[warp * 72 + 64] = ec0 * inv;
        __syncwarp();

        // Output: dims d=lane, d=lane+32
        float o0 = 0.f, o1 = 0.f;
#pragma unroll
        for (int widx = 0; widx < 65; ++widx) {
            float p = Ps[warp * 72 + widx];
            int j = qi + widx;
            o0 += p * Vs[j * WPAD_ + lane];
            o1 += p * Vs[j * WPAD_ + lane + 32];
        }
        float* optr = att + (size_t)(b * L_ + qpos) * E_ + h * HD_;
        optr[lane]      = o0;
        optr[lane + 32] = o1;
        __syncwarp();
    }
}

// ---------------------------------------------------------------------------
// kernel_launch
// Inputs (metadata order): x[f32 2*2048*1024], padding_mask[i32 2*2048],
// W_qkv[f32 3072*1024], b_qkv[f32 3072], W_o[f32 1024*1024], b_o[f32 1024]
// Output: f32 [2,2048,1024]
// ---------------------------------------------------------------------------
extern "C" void kernel_launch(void* const* d_in, const int* in_sizes, int n_in,
                              void* d_out, int out_size)
{
    const float* x      = (const float*)d_in[0];
    const int*   pmask  = (const int*)d_in[1];
    const float* W_qkv  = (const float*)d_in[2];
    const float* b_qkv  = (const float*)d_in[3];
    const float* W_o    = (const float*)d_in[4];
    const float* b_o    = (const float*)d_in[5];
    float* out = (float*)d_out;

    float* qkv_buf = nullptr;
    float* att_buf = nullptr;
    cudaGetSymbolAddress((void**)&qkv_buf, g_qkv);
    cudaGetSymbolAddress((void**)&att_buf, g_att);

    // Attention dynamic smem
    const int smem_attn = (SPAN_ * WPAD_ * 2 + 8 * 64 + 8 * 72) * (int)sizeof(float);
    static bool attr_done = false;
    if (!attr_done) {
        cudaFuncSetAttribute(swattn, cudaFuncAttributeMaxDynamicSharedMemorySize, smem_attn);
        attr_done = true;
    }

    // 1) QKV projection: [4096,1024] x [3072,1024]^T
    sgemm_nt<<<dim3(NQKV_ / 128, ML_ / 128), 256>>>(x, W_qkv, b_qkv, qkv_buf,
                                                    ML_, NQKV_, KD_);
    // 2) Sliding-window attention
    swattn<<<dim3(L_ / QT_, H_, B_), 256, smem_attn>>>(qkv_buf, pmask, att_buf);
    // 3) Output projection: [4096,1024] x [1024,1024]^T
    sgemm_nt<<<dim3(E_ / 128, ML_ / 128), 256>>>(att_buf, W_o, b_o, out,
                                                 ML_, E_, KD_);
}

// round 3
// speedup vs baseline: 2.0887x; 2.0887x over previous
#include <cuda_runtime.h>
#include <cuda_bf16.h>
#include <cstdint>
#include <math.h>

// Problem constants
#define B_    2
#define L_    2048
#define E_    1024
#define H_    16
#define HD_   64
#define KD_   1024
#define NQKV_ 3072
#define ML_   (B_*L_)   // 4096

// ---------------- GEMM tiling (mma.sync path; tcgen05 needs the 103a PTX
// target which this harness's compute_103 pass does not enable) -------------
#define BM 128
#define BN 128
#define BK 32
#define GEMM_THREADS 256
#define ROWB 80                     // 64B data + 16B pad (conflict-free ldsm)
#define ABYTES (256 * ROWB)         // hi rows 0..127, lo rows 128..255
#define STAGEB (2 * ABYTES)         // A block + B block
#define NSTAGE 3
#define GEMM_SMEM (NSTAGE * STAGEB) // 122880
#define LO_OFF (128 * ROWB)

// Attention tiling
#define QT_   64
#define SPAN_ 128
#define WPAD_ 65

// ---------------- scratch ----------------
__device__ float g_qkv[(size_t)ML_ * NQKV_];
__device__ float g_att[(size_t)ML_ * E_];
__device__ __nv_bfloat16 g_ah[(size_t)ML_ * KD_];
__device__ __nv_bfloat16 g_al[(size_t)ML_ * KD_];
__device__ __nv_bfloat16 g_wqh[(size_t)NQKV_ * KD_];
__device__ __nv_bfloat16 g_wql[(size_t)NQKV_ * KD_];
__device__ __nv_bfloat16 g_woh[(size_t)E_ * E_];
__device__ __nv_bfloat16 g_wol[(size_t)E_ * E_];

// ---------------- helpers ----------------
__device__ __forceinline__ uint32_t smem_u32(const void* p) {
    uint32_t a;
    asm("{ .reg .u64 t; cvta.to.shared.u64 t, %1; cvt.u32.u64 %0, t; }" : "=r"(a) : "l"(p));
    return a;
}
#define CP16(dst, src) \
    asm volatile("cp.async.cg.shared.global [%0], [%1], 16;" :: "r"(dst), "l"(src))
#define CP_COMMIT() asm volatile("cp.async.commit_group;" ::: "memory")
#define CP_WAIT(n)  asm volatile("cp.async.wait_group %0;" :: "n"(n) : "memory")

#define LDSM_X4(r0, r1, r2, r3, a) \
    asm volatile("ldmatrix.sync.aligned.m8n8.x4.shared.b16 {%0,%1,%2,%3}, [%4];" \
                 : "=r"(r0), "=r"(r1), "=r"(r2), "=r"(r3) : "r"(a))

__device__ __forceinline__ void mma_bf16(float c[4], const uint32_t a[4],
                                         uint32_t b0, uint32_t b1) {
    asm volatile(
        "mma.sync.aligned.m16n8k16.row.col.f32.bf16.bf16.f32 "
        "{%0,%1,%2,%3}, {%4,%5,%6,%7}, {%8,%9}, {%0,%1,%2,%3};"
        : "+f"(c[0]), "+f"(c[1]), "+f"(c[2]), "+f"(c[3])
        : "r"(a[0]), "r"(a[1]), "r"(a[2]), "r"(a[3]), "r"(b0), "r"(b1));
}

// ---------------------------------------------------------------------------
// C[M,N] = Ah*Bh^T + Ah*Bl^T + Al*Bh^T + bias    (fp32 out)
// A*: [M,K] bf16 row-major; B*: [N,K] bf16 row-major. M%128==0,N%128==0,K%32==0
// ---------------------------------------------------------------------------
__global__ __launch_bounds__(GEMM_THREADS, 1)
void gemm_mma(const __nv_bfloat16* __restrict__ Ah, const __nv_bfloat16* __restrict__ Al,
              const __nv_bfloat16* __restrict__ Bh, const __nv_bfloat16* __restrict__ Bl,
              const float* __restrict__ bias, float* __restrict__ C,
              int M, int N, int K)
{
    extern __shared__ char smem[];
    const uint32_t sbase = smem_u32(smem);
    const int tid  = threadIdx.x;
    const int lane = tid & 31;
    const int wid  = tid >> 5;
    const int warp_m = wid >> 1;     // 0..3 -> 32 rows each
    const int warp_n = wid & 1;      // 0..1 -> 64 cols each
    const int bm = blockIdx.y * BM;
    const int bn = blockIdx.x * BN;
    const int NT = K / BK;

    // ---- per-thread load geometry: 8 chunks of 16B per stage ----
    // global chunk g = i*256 + tid; r = g>>2 (0..511), c = g&3
    const __nv_bfloat16* srcp[8];
    uint32_t dsto[8];
#pragma unroll
    for (int i = 0; i < 8; ++i) {
        int g = i * 256 + tid;
        int r = g >> 2, c = g & 3;
        int reg = r >> 7, rr = r & 127;
        const __nv_bfloat16* base =
            (reg == 0) ? Ah + (size_t)(bm + rr) * K :
            (reg == 1) ? Al + (size_t)(bm + rr) * K :
            (reg == 2) ? Bh + (size_t)(bn + rr) * K :
                         Bl + (size_t)(bn + rr) * K;
        srcp[i] = base + c * 8;
        dsto[i] = (uint32_t)(r * ROWB + c * 16);
    }

    auto stage_load = [&](int stage, int kt) {
        uint32_t sb = sbase + stage * STAGEB;
        int koff = kt * BK;
#pragma unroll
        for (int i = 0; i < 8; ++i)
            CP16(sb + dsto[i], srcp[i] + koff);
    };

    // ---- fragment addresses ----
    const uint32_t aOff = (uint32_t)((warp_m * 32 + (lane & 15)) * ROWB + (lane >> 4) * 16);
    const uint32_t bOff = (uint32_t)(ABYTES +
        (warp_n * 64 + ((lane >> 4) << 3) + (lane & 7)) * ROWB + ((lane >> 3) & 1) * 16);

    float acc[2][8][4];
#pragma unroll
    for (int mt = 0; mt < 2; ++mt)
#pragma unroll
        for (int nt = 0; nt < 8; ++nt)
#pragma unroll
            for (int j = 0; j < 4; ++j) acc[mt][nt][j] = 0.0f;

    // ---- pipeline prologue ----
    stage_load(0, 0); CP_COMMIT();
    stage_load(1, 1); CP_COMMIT();

    for (int kt = 0; kt < NT; ++kt) {
        if (kt + 1 < NT) { CP_WAIT(1); } else { CP_WAIT(0); }
        __syncthreads();

        const uint32_t st = sbase + (kt % NSTAGE) * STAGEB;
#pragma unroll
        for (int s = 0; s < 2; ++s) {          // two k16 steps per BK=32
            uint32_t ah[2][4], al[2][4], bh[8][2], bl[8][2];
#pragma unroll
            for (int mt = 0; mt < 2; ++mt) {
                uint32_t a = st + aOff + mt * 16 * ROWB + s * 32;
                LDSM_X4(ah[mt][0], ah[mt][1], ah[mt][2], ah[mt][3], a);
                LDSM_X4(al[mt][0], al[mt][1], al[mt][2], al[mt][3], a + LO_OFF);
            }
#pragma unroll
            for (int p = 0; p < 4; ++p) {
                uint32_t a = st + bOff + p * 16 * ROWB + s * 32;
                LDSM_X4(bh[2*p][0], bh[2*p][1], bh[2*p+1][0], bh[2*p+1][1], a);
                LDSM_X4(bl[2*p][0], bl[2*p][1], bl[2*p+1][0], bl[2*p+1][1], a + LO_OFF);
            }
#pragma unroll
            for (int mt = 0; mt < 2; ++mt)
#pragma unroll
                for (int nt = 0; nt < 8; ++nt) {
                    mma_bf16(acc[mt][nt], ah[mt], bh[nt][0], bh[nt][1]);
                    mma_bf16(acc[mt][nt], ah[mt], bl[nt][0], bl[nt][1]);
                    mma_bf16(acc[mt][nt], al[mt], bh[nt][0], bh[nt][1]);
                }
        }

        if (kt + 2 < NT) { stage_load((kt + 2) % NSTAGE, kt + 2); CP_COMMIT(); }
    }

    // ---- epilogue ----
    const int r0 = bm + warp_m * 32 + (lane >> 2);
    const int c0 = bn + warp_n * 64 + (lane & 3) * 2;
#pragma unroll
    for (int mt = 0; mt < 2; ++mt) {
#pragma unroll
        for (int nt = 0; nt < 8; ++nt) {
            int col = c0 + nt * 8;
            float bx = bias[col], by = bias[col + 1];
            float2 v0 = make_float2(acc[mt][nt][0] + bx, acc[mt][nt][1] + by);
            float2 v1 = make_float2(acc[mt][nt][2] + bx, acc[mt][nt][3] + by);
            *(float2*)(C + (size_t)(r0 + mt * 16) * N + col)     = v0;
            *(float2*)(C + (size_t)(r0 + mt * 16 + 8) * N + col) = v1;
        }
    }
}

// ---------------------------------------------------------------------------
// fp32 -> bf16 hi/lo split
// ---------------------------------------------------------------------------
__global__ __launch_bounds__(256) void split_bf16(
    const float4* __restrict__ src, __nv_bfloat162* __restrict__ hi,
    __nv_bfloat162* __restrict__ lo, int n4)
{
    int i = blockIdx.x * blockDim.x + threadIdx.x;
    if (i >= n4) return;
    float4 v = src[i];
    __nv_bfloat16 h0 = __float2bfloat16(v.x);
    __nv_bfloat16 h1 = __float2bfloat16(v.y);
    __nv_bfloat16 h2 = __float2bfloat16(v.z);
    __nv_bfloat16 h3 = __float2bfloat16(v.w);
    __nv_bfloat16 l0 = __float2bfloat16(v.x - __bfloat162float(h0));
    __nv_bfloat16 l1 = __float2bfloat16(v.y - __bfloat162float(h1));
    __nv_bfloat16 l2 = __float2bfloat16(v.z - __bfloat162float(h2));
    __nv_bfloat16 l3 = __float2bfloat16(v.w - __bfloat162float(h3));
    hi[2 * i]     = __halves2bfloat162(h0, h1);
    hi[2 * i + 1] = __halves2bfloat162(h2, h3);
    lo[2 * i]     = __halves2bfloat162(l0, l1);
    lo[2 * i + 1] = __halves2bfloat162(l2, l3);
}

// ---------------------------------------------------------------------------
// Sliding-window attention (unchanged)
// ---------------------------------------------------------------------------
__global__ __launch_bounds__(256) void swattn(
    const float* __restrict__ qkv, const int* __restrict__ pmask,
    float* __restrict__ att)
{
    extern __shared__ float sm[];
    float* Ks = sm;
    float* Vs = Ks + SPAN_ * WPAD_;
    float* Qs = Vs + SPAN_ * WPAD_;
    float* Ps = Qs + 8 * 64;

    const int b  = blockIdx.z;
    const int h  = blockIdx.y;
    const int q0 = blockIdx.x * QT_;
    const int tid = threadIdx.x;

    for (int idx = tid; idx < SPAN_ * 16; idx += 256) {
        int row = idx >> 4;
        int c4  = (idx & 15) << 2;
        int pos = q0 - 32 + row;
        float4 kv = make_float4(0.f, 0.f, 0.f, 0.f);
        float4 vv = make_float4(0.f, 0.f, 0.f, 0.f);
        if (pos >= 0 && pos < L_) {
            const float* base = qkv + (size_t)(b * L_ + pos) * NQKV_ + h * 192;
            kv = *(const float4*)(base + 64  + c4);
            vv = *(const float4*)(base + 128 + c4);
        }
        Ks[row * WPAD_ + c4 + 0] = kv.x; Ks[row * WPAD_ + c4 + 1] = kv.y;
        Ks[row * WPAD_ + c4 + 2] = kv.z; Ks[row * WPAD_ + c4 + 3] = kv.w;
        Vs[row * WPAD_ + c4 + 0] = vv.x; Vs[row * WPAD_ + c4 + 1] = vv.y;
        Vs[row * WPAD_ + c4 + 2] = vv.z; Vs[row * WPAD_ + c4 + 3] = vv.w;
    }
    __syncthreads();

    const int warp = tid >> 5;
    const int lane = tid & 31;
    const float scale = 0.125f;
    const float NEGS  = -100000.0f * 0.125f;

    for (int iter = 0; iter < QT_ / 8; ++iter) {
        int qi   = iter * 8 + warp;
        int qpos = q0 + qi;

        const float* qptr = qkv + (size_t)(b * L_ + qpos) * NQKV_ + h * 192;
        Qs[warp * 64 + lane]      = qptr[lane];
        Qs[warp * 64 + lane + 32] = qptr[lane + 32];
        __syncwarp();

        int ja = qi + lane;
        float sa = 0.f, sb = 0.f, sc = 0.f;
#pragma unroll
        for (int d = 0; d < 64; ++d) {
            float qd = Qs[warp * 64 + d];
            sa += qd * Ks[ja * WPAD_ + d];
            sb += qd * Ks[(ja + 32) * WPAD_ + d];
        }
        if (lane == 0) {
            int jc = qi + 64;
#pragma unroll
            for (int d = 0; d < 64; ++d)
                sc += Qs[warp * 64 + d] * Ks[jc * WPAD_ + d];
        }

        int pa = qpos - 32 + lane;
        int pb = pa + 32;
        int pc = qpos + 32;
        bool oka = (pa >= 0 && pa < L_) && (pmask[b * L_ + (pa < 0 ? 0 : (pa >= L_ ? L_ - 1 : pa))] != 0);
        bool okb = (pb >= 0 && pb < L_) && (pmask[b * L_ + (pb < 0 ? 0 : (pb >= L_ ? L_ - 1 : pb))] != 0);
        bool okc = (pc >= 0 && pc < L_) && (pmask[b * L_ + (pc < 0 ? 0 : (pc >= L_ ? L_ - 1 : pc))] != 0);
        sa = oka ? sa * scale : NEGS;
        sb = okb ? sb * scale : NEGS;
        sc = okc ? sc * scale : NEGS;

        float m = fmaxf(sa, sb);
#pragma unroll
        for (int off = 16; off > 0; off >>= 1)
            m = fmaxf(m, __shfl_xor_sync(0xffffffffu, m, off));
        float sc0 = __shfl_sync(0xffffffffu, sc, 0);
        m = fmaxf(m, sc0);

        float ea = __expf(sa - m);
        float eb = __expf(sb - m);
        float ec0 = __expf(sc0 - m);
        float sum = ea + eb;
#pragma unroll
        for (int off = 16; off > 0; off >>= 1)
            sum += __shfl_xor_sync(0xffffffffu, sum, off);
        sum += ec0;
        float inv = 1.0f / sum;

        Ps[warp * 72 + lane]      = ea * inv;
        Ps[warp * 72 + lane + 32] = eb * inv;
        if (lane == 0) Ps[warp * 72 + 64] = ec0 * inv;
        __syncwarp();

        float o0 = 0.f, o1 = 0.f;
#pragma unroll
        for (int widx = 0; widx < 65; ++widx) {
            float p = Ps[warp * 72 + widx];
            int j = qi + widx;
            o0 += p * Vs[j * WPAD_ + lane];
            o1 += p * Vs[j * WPAD_ + lane + 32];
        }
        float* optr = att + (size_t)(b * L_ + qpos) * E_ + h * HD_;
        optr[lane]      = o0;
        optr[lane + 32] = o1;
        __syncwarp();
    }
}

// ---------------------------------------------------------------------------
// kernel_launch
// ---------------------------------------------------------------------------
extern "C" void kernel_launch(void* const* d_in, const int* in_sizes, int n_in,
                              void* d_out, int out_size)
{
    const float* x      = (const float*)d_in[0];
    const int*   pmask  = (const int*)d_in[1];
    const float* W_qkv  = (const float*)d_in[2];
    const float* b_qkv  = (const float*)d_in[3];
    const float* W_o    = (const float*)d_in[4];
    const float* b_o    = (const float*)d_in[5];
    float* out = (float*)d_out;

    float *qkv_buf, *att_buf;
    __nv_bfloat16 *ah, *al, *wqh, *wql, *woh, *wol;
    cudaGetSymbolAddress((void**)&qkv_buf, g_qkv);
    cudaGetSymbolAddress((void**)&att_buf, g_att);
    cudaGetSymbolAddress((void**)&ah, g_ah);
    cudaGetSymbolAddress((void**)&al, g_al);
    cudaGetSymbolAddress((void**)&wqh, g_wqh);
    cudaGetSymbolAddress((void**)&wql, g_wql);
    cudaGetSymbolAddress((void**)&woh, g_woh);
    cudaGetSymbolAddress((void**)&wol, g_wol);

    const int smem_attn = (SPAN_ * WPAD_ * 2 + 8 * 64 + 8 * 72) * (int)sizeof(float);
    static bool attr_done = false;
    if (!attr_done) {
        cudaFuncSetAttribute(swattn, cudaFuncAttributeMaxDynamicSharedMemorySize, smem_attn);
        cudaFuncSetAttribute(gemm_mma, cudaFuncAttributeMaxDynamicSharedMemorySize, GEMM_SMEM);
        attr_done = true;
    }

    // 1) split x and W_qkv to bf16 hi/lo
    {
        int n4 = (ML_ * KD_) / 4;
        split_bf16<<<(n4 + 255) / 256, 256>>>((const float4*)x,
            (__nv_bfloat162*)ah, (__nv_bfloat162*)al, n4);
        int w4 = (NQKV_ * KD_) / 4;
        split_bf16<<<(w4 + 255) / 256, 256>>>((const float4*)W_qkv,
            (__nv_bfloat162*)wqh, (__nv_bfloat162*)wql, w4);
    }
    // 2) QKV projection on tensor cores
    gemm_mma<<<dim3(NQKV_ / BN, ML_ / BM), GEMM_THREADS, GEMM_SMEM>>>(
        ah, al, wqh, wql, b_qkv, qkv_buf, ML_, NQKV_, KD_);
    // 3) sliding-window attention (fp32)
    swattn<<<dim3(L_ / QT_, H_, B_), 256, smem_attn>>>(qkv_buf, pmask, att_buf);
    // 4) split attention output and W_o
    {
        int n4 = (ML_ * E_) / 4;
        split_bf16<<<(n4 + 255) / 256, 256>>>((const float4*)att_buf,
            (__nv_bfloat162*)ah, (__nv_bfloat162*)al, n4);
        int w4 = (E_ * E_) / 4;
        split_bf16<<<(w4 + 255) / 256, 256>>>((const float4*)W_o,
            (__nv_bfloat162*)woh, (__nv_bfloat162*)wol, w4);
    }
    // 5) output projection on tensor cores
    gemm_mma<<<dim3(E_ / BN, ML_ / BM), GEMM_THREADS, GEMM_SMEM>>>(
        ah, al, woh, wol, b_o, out, ML_, E_, KD_);
}

// round 4
// speedup vs baseline: 2.3505x; 1.1253x over previous
#include <cuda_runtime.h>
#include <cuda_bf16.h>
#include <cstdint>
#include <math.h>

// Problem constants
#define B_    2
#define L_    2048
#define E_    1024
#define H_    16
#define HD_   64
#define KD_   1024
#define NQKV_ 3072
#define ML_   (B_*L_)   // 4096

// ---------------- GEMM tiling ----------------
#define BM 128
#define BN 128
#define BK 32
#define GEMM_THREADS 256
#define ROWB 80
#define ABYTES (256 * ROWB)
#define STAGEB (2 * ABYTES)
#define NSTAGE 3
#define GEMM_SMEM (NSTAGE * STAGEB) // 122880
#define LO_OFF (128 * ROWB)

// ---------------- attention tiling ----------------
#define AROWB 144              // 72 bf16 per row; stride 9 x 16B -> conflict-free ldsm
#define S_QH 0
#define S_QL (S_QH + 64*AROWB)
#define S_KH (S_QL + 64*AROWB)
#define S_KL (S_KH + 128*AROWB)
#define S_VH (S_KL + 128*AROWB)
#define S_VL (S_VH + 128*AROWB)
#define S_OK (S_VL + 128*AROWB)
#define ATTN_SMEM (S_OK + 128*4)   // 92672

// ---------------- scratch ----------------
__device__ __nv_bfloat16 g_qkvh[(size_t)ML_ * NQKV_];
__device__ __nv_bfloat16 g_qkvl[(size_t)ML_ * NQKV_];
__device__ __nv_bfloat16 g_xh[(size_t)ML_ * KD_];
__device__ __nv_bfloat16 g_xl[(size_t)ML_ * KD_];
__device__ __nv_bfloat16 g_oh[(size_t)ML_ * E_];
__device__ __nv_bfloat16 g_ol[(size_t)ML_ * E_];
__device__ __nv_bfloat16 g_wqh[(size_t)NQKV_ * KD_];
__device__ __nv_bfloat16 g_wql[(size_t)NQKV_ * KD_];
__device__ __nv_bfloat16 g_woh[(size_t)E_ * E_];
__device__ __nv_bfloat16 g_wol[(size_t)E_ * E_];

// ---------------- helpers ----------------
__device__ __forceinline__ uint32_t smem_u32(const void* p) {
    uint32_t a;
    asm("{ .reg .u64 t; cvta.to.shared.u64 t, %1; cvt.u32.u64 %0, t; }" : "=r"(a) : "l"(p));
    return a;
}
#define CP16(dst, src) \
    asm volatile("cp.async.cg.shared.global [%0], [%1], 16;" :: "r"(dst), "l"(src))
#define CP_COMMIT() asm volatile("cp.async.commit_group;" ::: "memory")
#define CP_WAIT(n)  asm volatile("cp.async.wait_group %0;" :: "n"(n) : "memory")

#define LDSM_X4(r0, r1, r2, r3, a) \
    asm volatile("ldmatrix.sync.aligned.m8n8.x4.shared.b16 {%0,%1,%2,%3}, [%4];" \
                 : "=r"(r0), "=r"(r1), "=r"(r2), "=r"(r3) : "r"(a))
#define LDSM_X4_T(r0, r1, r2, r3, a) \
    asm volatile("ldmatrix.sync.aligned.m8n8.x4.trans.shared.b16 {%0,%1,%2,%3}, [%4];" \
                 : "=r"(r0), "=r"(r1), "=r"(r2), "=r"(r3) : "r"(a))

__device__ __forceinline__ void mma_bf16(float c[4], const uint32_t a[4],
                                         uint32_t b0, uint32_t b1) {
    asm volatile(
        "mma.sync.aligned.m16n8k16.row.col.f32.bf16.bf16.f32 "
        "{%0,%1,%2,%3}, {%4,%5,%6,%7}, {%8,%9}, {%0,%1,%2,%3};"
        : "+f"(c[0]), "+f"(c[1]), "+f"(c[2]), "+f"(c[3])
        : "r"(a[0]), "r"(a[1]), "r"(a[2]), "r"(a[3]), "r"(b0), "r"(b1));
}

__device__ __forceinline__ void hilo2(float x, float y, uint32_t& hi, uint32_t& lo) {
    __nv_bfloat16 hx = __float2bfloat16(x), hy = __float2bfloat16(y);
    __nv_bfloat162 h2 = __halves2bfloat162(hx, hy);
    __nv_bfloat162 l2 = __halves2bfloat162(__float2bfloat16(x - __bfloat162float(hx)),
                                           __float2bfloat16(y - __bfloat162float(hy)));
    hi = *(uint32_t*)&h2;
    lo = *(uint32_t*)&l2;
}

// ---------------------------------------------------------------------------
// C[M,N] = Ah*Bh^T + Ah*Bl^T + Al*Bh^T + bias
// HILO=false: fp32 out to Cf.  HILO=true: bf16 hi/lo out to Ch/Cl.
// ---------------------------------------------------------------------------
template<bool HILO>
__global__ __launch_bounds__(GEMM_THREADS, 1)
void gemm_mma(const __nv_bfloat16* __restrict__ Ah, const __nv_bfloat16* __restrict__ Al,
              const __nv_bfloat16* __restrict__ Bh, const __nv_bfloat16* __restrict__ Bl,
              const float* __restrict__ bias, float* __restrict__ Cf,
              uint32_t* __restrict__ Ch, uint32_t* __restrict__ Cl,
              int M, int N, int K)
{
    extern __shared__ char smem[];
    const uint32_t sbase = smem_u32(smem);
    const int tid  = threadIdx.x;
    const int lane = tid & 31;
    const int wid  = tid >> 5;
    const int warp_m = wid >> 1;
    const int warp_n = wid & 1;
    const int bm = blockIdx.y * BM;
    const int bn = blockIdx.x * BN;
    const int NT = K / BK;

    const __nv_bfloat16* srcp[8];
    uint32_t dsto[8];
#pragma unroll
    for (int i = 0; i < 8; ++i) {
        int g = i * 256 + tid;
        int r = g >> 2, c = g & 3;
        int reg = r >> 7, rr = r & 127;
        const __nv_bfloat16* base =
            (reg == 0) ? Ah + (size_t)(bm + rr) * K :
            (reg == 1) ? Al + (size_t)(bm + rr) * K :
            (reg == 2) ? Bh + (size_t)(bn + rr) * K :
                         Bl + (size_t)(bn + rr) * K;
        srcp[i] = base + c * 8;
        dsto[i] = (uint32_t)(r * ROWB + c * 16);
    }

    auto stage_load = [&](int stage, int kt) {
        uint32_t sb = sbase + stage * STAGEB;
        int koff = kt * BK;
#pragma unroll
        for (int i = 0; i < 8; ++i)
            CP16(sb + dsto[i], srcp[i] + koff);
    };

    const uint32_t aOff = (uint32_t)((warp_m * 32 + (lane & 15)) * ROWB + (lane >> 4) * 16);
    const uint32_t bOff = (uint32_t)(ABYTES +
        (warp_n * 64 + ((lane >> 4) << 3) + (lane & 7)) * ROWB + ((lane >> 3) & 1) * 16);

    float acc[2][8][4];
#pragma unroll
    for (int mt = 0; mt < 2; ++mt)
#pragma unroll
        for (int nt = 0; nt < 8; ++nt)
#pragma unroll
            for (int j = 0; j < 4; ++j) acc[mt][nt][j] = 0.0f;

    stage_load(0, 0); CP_COMMIT();
    stage_load(1, 1); CP_COMMIT();

    for (int kt = 0; kt < NT; ++kt) {
        if (kt + 1 < NT) { CP_WAIT(1); } else { CP_WAIT(0); }
        __syncthreads();

        const uint32_t st = sbase + (kt % NSTAGE) * STAGEB;
#pragma unroll
        for (int s = 0; s < 2; ++s) {
            uint32_t ah[2][4], al[2][4], bh[8][2], bl[8][2];
#pragma unroll
            for (int mt = 0; mt < 2; ++mt) {
                uint32_t a = st + aOff + mt * 16 * ROWB + s * 32;
                LDSM_X4(ah[mt][0], ah[mt][1], ah[mt][2], ah[mt][3], a);
                LDSM_X4(al[mt][0], al[mt][1], al[mt][2], al[mt][3], a + LO_OFF);
            }
#pragma unroll
            for (int p = 0; p < 4; ++p) {
                uint32_t a = st + bOff + p * 16 * ROWB + s * 32;
                LDSM_X4(bh[2*p][0], bh[2*p][1], bh[2*p+1][0], bh[2*p+1][1], a);
                LDSM_X4(bl[2*p][0], bl[2*p][1], bl[2*p+1][0], bl[2*p+1][1], a + LO_OFF);
            }
#pragma unroll
            for (int mt = 0; mt < 2; ++mt)
#pragma unroll
                for (int nt = 0; nt < 8; ++nt) {
                    mma_bf16(acc[mt][nt], ah[mt], bh[nt][0], bh[nt][1]);
                    mma_bf16(acc[mt][nt], ah[mt], bl[nt][0], bl[nt][1]);
                    mma_bf16(acc[mt][nt], al[mt], bh[nt][0], bh[nt][1]);
                }
        }

        if (kt + 2 < NT) { stage_load((kt + 2) % NSTAGE, kt + 2); CP_COMMIT(); }
    }

    const int r0 = bm + warp_m * 32 + (lane >> 2);
    const int c0 = bn + warp_n * 64 + (lane & 3) * 2;
#pragma unroll
    for (int mt = 0; mt < 2; ++mt) {
#pragma unroll
        for (int nt = 0; nt < 8; ++nt) {
            int col = c0 + nt * 8;
            float bx = bias[col], by = bias[col + 1];
            float vx0 = acc[mt][nt][0] + bx, vy0 = acc[mt][nt][1] + by;
            float vx1 = acc[mt][nt][2] + bx, vy1 = acc[mt][nt][3] + by;
            int ra = r0 + mt * 16, rb = ra + 8;
            if (HILO) {
                uint32_t h0, l0, h1, l1;
                hilo2(vx0, vy0, h0, l0);
                hilo2(vx1, vy1, h1, l1);
                size_t p0 = (size_t)ra * (N >> 1) + (col >> 1);
                size_t p1 = (size_t)rb * (N >> 1) + (col >> 1);
                Ch[p0] = h0; Cl[p0] = l0;
                Ch[p1] = h1; Cl[p1] = l1;
            } else {
                *(float2*)(Cf + (size_t)ra * N + col) = make_float2(vx0, vy0);
                *(float2*)(Cf + (size_t)rb * N + col) = make_float2(vx1, vy1);
            }
        }
    }
}

// ---------------------------------------------------------------------------
// fp32 -> bf16 hi/lo split
// ---------------------------------------------------------------------------
__global__ __launch_bounds__(256) void split_bf16(
    const float4* __restrict__ src, __nv_bfloat162* __restrict__ hi,
    __nv_bfloat162* __restrict__ lo, int n4)
{
    int i = blockIdx.x * blockDim.x + threadIdx.x;
    if (i >= n4) return;
    float4 v = src[i];
    __nv_bfloat16 h0 = __float2bfloat16(v.x);
    __nv_bfloat16 h1 = __float2bfloat16(v.y);
    __nv_bfloat16 h2 = __float2bfloat16(v.z);
    __nv_bfloat16 h3 = __float2bfloat16(v.w);
    __nv_bfloat16 l0 = __float2bfloat16(v.x - __bfloat162float(h0));
    __nv_bfloat16 l1 = __float2bfloat16(v.y - __bfloat162float(h1));
    __nv_bfloat16 l2 = __float2bfloat16(v.z - __bfloat162float(h2));
    __nv_bfloat16 l3 = __float2bfloat16(v.w - __bfloat162float(h3));
    hi[2 * i]     = __halves2bfloat162(h0, h1);
    hi[2 * i + 1] = __halves2bfloat162(h2, h3);
    lo[2 * i]     = __halves2bfloat162(l0, l1);
    lo[2 * i + 1] = __halves2bfloat162(l2, l3);
}

// ---------------------------------------------------------------------------
// Tensor-core sliding-window attention.
// Grid (L/64, H, B), 128 threads (4 warps). Warp w handles q rows w*16..+15.
// S = Q K^T (3-product hi/lo), masked softmax in fragments, O = P V
// (3-product), output written as bf16 hi/lo for the O-projection GEMM.
// ---------------------------------------------------------------------------
__global__ __launch_bounds__(128, 1) void attn_mma(
    const __nv_bfloat16* __restrict__ qkvh, const __nv_bfloat16* __restrict__ qkvl,
    const int* __restrict__ pmask,
    uint32_t* __restrict__ Oh, uint32_t* __restrict__ Ol)
{
    extern __shared__ char smem[];
    const uint32_t sb = smem_u32(smem);
    const int b = blockIdx.z, h = blockIdx.y, q0 = blockIdx.x * 64;
    const int tid = threadIdx.x, lane = tid & 31, w = tid >> 5;

    // ---- stage Q (64 rows), K/V (128 rows, bounds-checked) ----
    for (int i = tid; i < 64 * 8; i += 128) {
        int r = i >> 3, c = i & 7;
        size_t g = (size_t)(b * L_ + q0 + r) * NQKV_ + h * 192 + c * 8;
        *(uint4*)(smem + S_QH + r * AROWB + c * 16) = *(const uint4*)(qkvh + g);
        *(uint4*)(smem + S_QL + r * AROWB + c * 16) = *(const uint4*)(qkvl + g);
    }
    for (int i = tid; i < 128 * 8; i += 128) {
        int r = i >> 3, c = i & 7;
        int pos = q0 - 32 + r;
        uint4 z = make_uint4(0, 0, 0, 0);
        uint4 kh = z, kl = z, vh = z, vl = z;
        if (pos >= 0 && pos < L_) {
            size_t g = (size_t)(b * L_ + pos) * NQKV_ + h * 192 + c * 8;
            kh = *(const uint4*)(qkvh + g + 64);
            kl = *(const uint4*)(qkvl + g + 64);
            vh = *(const uint4*)(qkvh + g + 128);
            vl = *(const uint4*)(qkvl + g + 128);
        }
        *(uint4*)(smem + S_KH + r * AROWB + c * 16) = kh;
        *(uint4*)(smem + S_KL + r * AROWB + c * 16) = kl;
        *(uint4*)(smem + S_VH + r * AROWB + c * 16) = vh;
        *(uint4*)(smem + S_VL + r * AROWB + c * 16) = vl;
    }
    {
        int pos = q0 - 32 + tid;
        int ok = 0;
        if (pos >= 0 && pos < L_) ok = (pmask[b * L_ + pos] != 0);
        ((int*)(smem + S_OK))[tid] = ok;
    }
    __syncthreads();
    const int* okk = (const int*)(smem + S_OK);

    // ---- S = Q K^T ----
    float S[16][4];
#pragma unroll
    for (int i = 0; i < 16; ++i)
#pragma unroll
        for (int j = 0; j < 4; ++j) S[i][j] = 0.0f;

    uint32_t qfh[4][4], qfl[4][4];
    {
        uint32_t aoff = (uint32_t)((w * 16 + (lane & 15)) * AROWB + (lane >> 4) * 16);
#pragma unroll
        for (int ks = 0; ks < 4; ++ks) {
            LDSM_X4(qfh[ks][0], qfh[ks][1], qfh[ks][2], qfh[ks][3], sb + S_QH + aoff + ks * 32);
            LDSM_X4(qfl[ks][0], qfl[ks][1], qfl[ks][2], qfl[ks][3], sb + S_QL + aoff + ks * 32);
        }
    }
    {
        uint32_t boff = (uint32_t)(((((lane >> 4) << 3) + (lane & 7)) * AROWB) + ((lane >> 3) & 1) * 16);
#pragma unroll
        for (int kb = 0; kb < 8; ++kb) {
            uint32_t base = boff + kb * 16 * AROWB;
#pragma unroll
            for (int ks = 0; ks < 4; ++ks) {
                uint32_t bh0, bh1, bh2, bh3, bl0, bl1, bl2, bl3;
                LDSM_X4(bh0, bh1, bh2, bh3, sb + S_KH + base + ks * 32);
                LDSM_X4(bl0, bl1, bl2, bl3, sb + S_KL + base + ks * 32);
                mma_bf16(S[2 * kb],     qfh[ks], bh0, bh1);
                mma_bf16(S[2 * kb],     qfh[ks], bl0, bl1);
                mma_bf16(S[2 * kb],     qfl[ks], bh0, bh1);
                mma_bf16(S[2 * kb + 1], qfh[ks], bh2, bh3);
                mma_bf16(S[2 * kb + 1], qfh[ks], bl2, bl3);
                mma_bf16(S[2 * kb + 1], qfl[ks], bh2, bh3);
            }
        }
    }

    // ---- mask + softmax (reference semantics: NEG=-1e5 then /8) ----
    const int rlo = w * 16 + (lane >> 2);
    const int rhi = rlo + 8;
    const float scale = 0.125f;
    const float NEGS = -12500.0f;
    float mlo = -3.0e38f, mhi = -3.0e38f;
#pragma unroll
    for (int nb = 0; nb < 16; ++nb) {
#pragma unroll
        for (int p = 0; p < 2; ++p) {
            int col = nb * 8 + (lane & 3) * 2 + p;
            float s0 = S[nb][p];
            int d0 = col - rlo;
            s0 = (d0 >= 0 && d0 <= 64) ? (okk[col] ? s0 * scale : NEGS) : -3.0e38f;
            S[nb][p] = s0;
            mlo = fmaxf(mlo, s0);
            float s1 = S[nb][2 + p];
            int d1 = col - rhi;
            s1 = (d1 >= 0 && d1 <= 64) ? (okk[col] ? s1 * scale : NEGS) : -3.0e38f;
            S[nb][2 + p] = s1;
            mhi = fmaxf(mhi, s1);
        }
    }
#pragma unroll
    for (int o = 1; o <= 2; o <<= 1) {
        mlo = fmaxf(mlo, __shfl_xor_sync(0xffffffffu, mlo, o));
        mhi = fmaxf(mhi, __shfl_xor_sync(0xffffffffu, mhi, o));
    }
    float slo = 0.f, shi = 0.f;
#pragma unroll
    for (int nb = 0; nb < 16; ++nb) {
#pragma unroll
        for (int p = 0; p < 2; ++p) {
            float e0 = __expf(S[nb][p] - mlo);     S[nb][p] = e0;     slo += e0;
            float e1 = __expf(S[nb][2 + p] - mhi); S[nb][2 + p] = e1; shi += e1;
        }
    }
#pragma unroll
    for (int o = 1; o <= 2; o <<= 1) {
        slo += __shfl_xor_sync(0xffffffffu, slo, o);
        shi += __shfl_xor_sync(0xffffffffu, shi, o);
    }
    const float invlo = 1.0f / slo;
    const float invhi = 1.0f / shi;

    // ---- P fragments (register-only hi/lo split) ----
    uint32_t ph[8][4], pl[8][4];
#pragma unroll
    for (int kb = 0; kb < 8; ++kb) {
        hilo2(S[2 * kb][0] * invlo,     S[2 * kb][1] * invlo,     ph[kb][0], pl[kb][0]);
        hilo2(S[2 * kb][2] * invhi,     S[2 * kb][3] * invhi,     ph[kb][1], pl[kb][1]);
        hilo2(S[2 * kb + 1][0] * invlo, S[2 * kb + 1][1] * invlo, ph[kb][2], pl[kb][2]);
        hilo2(S[2 * kb + 1][2] * invhi, S[2 * kb + 1][3] * invhi, ph[kb][3], pl[kb][3]);
    }

    // ---- O = P V ----
    float O[8][4];
#pragma unroll
    for (int i = 0; i < 8; ++i)
#pragma unroll
        for (int j = 0; j < 4; ++j) O[i][j] = 0.0f;

    {
        uint32_t voff = (uint32_t)((lane & 15) * AROWB + (lane >> 4) * 16);
#pragma unroll
        for (int kb = 0; kb < 8; ++kb) {
            uint32_t base = voff + kb * 16 * AROWB;
#pragma unroll
            for (int db = 0; db < 4; ++db) {
                uint32_t vh0, vh1, vh2, vh3, vl0, vl1, vl2, vl3;
                LDSM_X4_T(vh0, vh1, vh2, vh3, sb + S_VH + base + db * 32);
                LDSM_X4_T(vl0, vl1, vl2, vl3, sb + S_VL + base + db * 32);
                mma_bf16(O[2 * db],     ph[kb], vh0, vh1);
                mma_bf16(O[2 * db],     ph[kb], vl0, vl1);
                mma_bf16(O[2 * db],     pl[kb], vh0, vh1);
                mma_bf16(O[2 * db + 1], ph[kb], vh2, vh3);
                mma_bf16(O[2 * db + 1], ph[kb], vl2, vl3);
                mma_bf16(O[2 * db + 1], pl[kb], vh2, vh3);
            }
        }
    }

    // ---- write O as bf16 hi/lo [ML, E] ----
    const size_t rowlo = (size_t)(b * L_ + q0 + rlo);
    const size_t rowhi = rowlo + 8;
#pragma unroll
    for (int nb = 0; nb < 8; ++nb) {
        int col = h * 64 + nb * 8 + (lane & 3) * 2;
        uint32_t h0, l0, h1, l1;
        hilo2(O[nb][0], O[nb][1], h0, l0);
        hilo2(O[nb][2], O[nb][3], h1, l1);
        Oh[rowlo * (E_ / 2) + (col >> 1)] = h0;
        Ol[rowlo * (E_ / 2) + (col >> 1)] = l0;
        Oh[rowhi * (E_ / 2) + (col >> 1)] = h1;
        Ol[rowhi * (E_ / 2) + (col >> 1)] = l1;
    }
}

// ---------------------------------------------------------------------------
// kernel_launch
// ---------------------------------------------------------------------------
extern "C" void kernel_launch(void* const* d_in, const int* in_sizes, int n_in,
                              void* d_out, int out_size)
{
    const float* x      = (const float*)d_in[0];
    const int*   pmask  = (const int*)d_in[1];
    const float* W_qkv  = (const float*)d_in[2];
    const float* b_qkv  = (const float*)d_in[3];
    const float* W_o    = (const float*)d_in[4];
    const float* b_o    = (const float*)d_in[5];
    float* out = (float*)d_out;

    __nv_bfloat16 *qkvh, *qkvl, *xh, *xl, *oh, *ol, *wqh, *wql, *woh, *wol;
    cudaGetSymbolAddress((void**)&qkvh, g_qkvh);
    cudaGetSymbolAddress((void**)&qkvl, g_qkvl);
    cudaGetSymbolAddress((void**)&xh, g_xh);
    cudaGetSymbolAddress((void**)&xl, g_xl);
    cudaGetSymbolAddress((void**)&oh, g_oh);
    cudaGetSymbolAddress((void**)&ol, g_ol);
    cudaGetSymbolAddress((void**)&wqh, g_wqh);
    cudaGetSymbolAddress((void**)&wql, g_wql);
    cudaGetSymbolAddress((void**)&woh, g_woh);
    cudaGetSymbolAddress((void**)&wol, g_wol);

    static bool attr_done = false;
    if (!attr_done) {
        cudaFuncSetAttribute(gemm_mma<false>, cudaFuncAttributeMaxDynamicSharedMemorySize, GEMM_SMEM);
        cudaFuncSetAttribute(gemm_mma<true>,  cudaFuncAttributeMaxDynamicSharedMemorySize, GEMM_SMEM);
        cudaFuncSetAttribute(attn_mma, cudaFuncAttributeMaxDynamicSharedMemorySize, ATTN_SMEM);
        attr_done = true;
    }

    // 1) splits for GEMM inputs
    {
        int n4 = (ML_ * KD_) / 4;
        split_bf16<<<(n4 + 255) / 256, 256>>>((const float4*)x,
            (__nv_bfloat162*)xh, (__nv_bfloat162*)xl, n4);
        int w4 = (NQKV_ * KD_) / 4;
        split_bf16<<<(w4 + 255) / 256, 256>>>((const float4*)W_qkv,
            (__nv_bfloat162*)wqh, (__nv_bfloat162*)wql, w4);
        int o4 = (E_ * E_) / 4;
        split_bf16<<<(o4 + 255) / 256, 256>>>((const float4*)W_o,
            (__nv_bfloat162*)woh, (__nv_bfloat162*)wol, o4);
    }
    // 2) QKV projection -> bf16 hi/lo
    gemm_mma<true><<<dim3(NQKV_ / BN, ML_ / BM), GEMM_THREADS, GEMM_SMEM>>>(
        xh, xl, wqh, wql, b_qkv, nullptr,
        (uint32_t*)qkvh, (uint32_t*)qkvl, ML_, NQKV_, KD_);
    // 3) tensor-core sliding-window attention -> bf16 hi/lo
    attn_mma<<<dim3(L_ / 64, H_, B_), 128, ATTN_SMEM>>>(
        qkvh, qkvl, pmask, (uint32_t*)oh, (uint32_t*)ol);
    // 4) output projection -> fp32
    gemm_mma<false><<<dim3(E_ / BN, ML_ / BM), GEMM_THREADS, GEMM_SMEM>>>(
        oh, ol, woh, wol, b_o, out, nullptr, nullptr, ML_, E_, KD_);
}

// round 5
// speedup vs baseline: 2.3766x; 1.0111x over previous
#include <cuda_runtime.h>
#include <cuda_bf16.h>
#include <cstdint>
#include <math.h>

// Problem constants
#define B_    2
#define L_    2048
#define E_    1024
#define H_    16
#define HD_   64
#define KD_   1024
#define NQKV_ 3072
#define ML_   (B_*L_)   // 4096

// ---------------- GEMM tiling ----------------
#define BM 128
#define BN 128
#define BK 64
#define GEMM_THREADS 512
#define ROWB 144                    // 128B data + 16B pad (conflict-free ldsm)
#define LO_OFF  (128 * ROWB)
#define B_OFF   (256 * ROWB)
#define STAGEB  (512 * ROWB)        // 73728
#define NSTAGE 2
#define GEMM_SMEM (NSTAGE * STAGEB) // 147456

// ---------------- attention tiling ----------------
#define AROWB 144
#define S_QH 0
#define S_QL (S_QH + 64*AROWB)
#define S_KH (S_QL + 64*AROWB)
#define S_KL (S_KH + 128*AROWB)
#define S_VH (S_KL + 128*AROWB)
#define S_VL (S_VH + 128*AROWB)
#define S_OK (S_VL + 128*AROWB)
#define ATTN_SMEM (S_OK + 128*4)

// ---------------- scratch ----------------
__device__ __nv_bfloat16 g_qkvh[(size_t)ML_ * NQKV_];
__device__ __nv_bfloat16 g_qkvl[(size_t)ML_ * NQKV_];
__device__ __nv_bfloat16 g_xh[(size_t)ML_ * KD_];
__device__ __nv_bfloat16 g_xl[(size_t)ML_ * KD_];
__device__ __nv_bfloat16 g_oh[(size_t)ML_ * E_];
__device__ __nv_bfloat16 g_ol[(size_t)ML_ * E_];
__device__ __nv_bfloat16 g_wqh[(size_t)NQKV_ * KD_];
__device__ __nv_bfloat16 g_wql[(size_t)NQKV_ * KD_];
__device__ __nv_bfloat16 g_woh[(size_t)E_ * E_];
__device__ __nv_bfloat16 g_wol[(size_t)E_ * E_];

// ---------------- helpers ----------------
__device__ __forceinline__ uint32_t smem_u32(const void* p) {
    uint32_t a;
    asm("{ .reg .u64 t; cvta.to.shared.u64 t, %1; cvt.u32.u64 %0, t; }" : "=r"(a) : "l"(p));
    return a;
}
#define CP16(dst, src) \
    asm volatile("cp.async.cg.shared.global [%0], [%1], 16;" :: "r"(dst), "l"(src))
#define CP_COMMIT() asm volatile("cp.async.commit_group;" ::: "memory")
#define CP_WAIT(n)  asm volatile("cp.async.wait_group %0;" :: "n"(n) : "memory")

#define LDSM_X4(r0, r1, r2, r3, a) \
    asm volatile("ldmatrix.sync.aligned.m8n8.x4.shared.b16 {%0,%1,%2,%3}, [%4];" \
                 : "=r"(r0), "=r"(r1), "=r"(r2), "=r"(r3) : "r"(a))
#define LDSM_X4_T(r0, r1, r2, r3, a) \
    asm volatile("ldmatrix.sync.aligned.m8n8.x4.trans.shared.b16 {%0,%1,%2,%3}, [%4];" \
                 : "=r"(r0), "=r"(r1), "=r"(r2), "=r"(r3) : "r"(a))

__device__ __forceinline__ void mma_bf16(float c[4], const uint32_t a[4],
                                         uint32_t b0, uint32_t b1) {
    asm volatile(
        "mma.sync.aligned.m16n8k16.row.col.f32.bf16.bf16.f32 "
        "{%0,%1,%2,%3}, {%4,%5,%6,%7}, {%8,%9}, {%0,%1,%2,%3};"
        : "+f"(c[0]), "+f"(c[1]), "+f"(c[2]), "+f"(c[3])
        : "r"(a[0]), "r"(a[1]), "r"(a[2]), "r"(a[3]), "r"(b0), "r"(b1));
}

__device__ __forceinline__ void hilo2(float x, float y, uint32_t& hi, uint32_t& lo) {
    __nv_bfloat16 hx = __float2bfloat16(x), hy = __float2bfloat16(y);
    __nv_bfloat162 h2 = __halves2bfloat162(hx, hy);
    __nv_bfloat162 l2 = __halves2bfloat162(__float2bfloat16(x - __bfloat162float(hx)),
                                           __float2bfloat16(y - __bfloat162float(hy)));
    hi = *(uint32_t*)&h2;
    lo = *(uint32_t*)&l2;
}

// ---------------------------------------------------------------------------
// C[M,N] = Ah*Bh^T + Ah*Bl^T + Al*Bh^T + bias
// 512 threads, 4x4 warp grid, warp tile 32x32, BK=64, 2-stage cp.async.
// ---------------------------------------------------------------------------
template<bool HILO>
__global__ __launch_bounds__(GEMM_THREADS, 1)
void gemm_mma(const __nv_bfloat16* __restrict__ Ah, const __nv_bfloat16* __restrict__ Al,
              const __nv_bfloat16* __restrict__ Bh, const __nv_bfloat16* __restrict__ Bl,
              const float* __restrict__ bias, float* __restrict__ Cf,
              uint32_t* __restrict__ Ch, uint32_t* __restrict__ Cl,
              int M, int N, int K)
{
    extern __shared__ char smem[];
    const uint32_t sbase = smem_u32(smem);
    const int tid  = threadIdx.x;
    const int lane = tid & 31;
    const int wid  = tid >> 5;
    const int warp_m = wid >> 2;     // 0..3 -> rows warp_m*32
    const int warp_n = wid & 3;      // 0..3 -> cols warp_n*32
    const int bm = blockIdx.y * BM;
    const int bn = blockIdx.x * BN;
    const int NT = K / BK;

    // ---- per-thread load geometry: 8 chunks of 16B per stage ----
    // g = i*512 + tid; r = g>>3 (0..511), c = g&7 (16B chunk in 128B row)
    const __nv_bfloat16* srcp[8];
    uint32_t dsto[8];
#pragma unroll
    for (int i = 0; i < 8; ++i) {
        int g = i * 512 + tid;
        int r = g >> 3, c = g & 7;
        int reg = r >> 7, rr = r & 127;
        const __nv_bfloat16* base =
            (reg == 0) ? Ah + (size_t)(bm + rr) * K :
            (reg == 1) ? Al + (size_t)(bm + rr) * K :
            (reg == 2) ? Bh + (size_t)(bn + rr) * K :
                         Bl + (size_t)(bn + rr) * K;
        srcp[i] = base + c * 8;
        dsto[i] = (uint32_t)(r * ROWB + c * 16);
    }

    auto stage_load = [&](int stage, int kt) {
        uint32_t sb = sbase + stage * STAGEB;
        int koff = kt * BK;
#pragma unroll
        for (int i = 0; i < 8; ++i)
            CP16(sb + dsto[i], srcp[i] + koff);
    };

    const uint32_t aOff = (uint32_t)((warp_m * 32 + (lane & 15)) * ROWB + (lane >> 4) * 16);
    const uint32_t bOff = (uint32_t)(B_OFF +
        (warp_n * 32 + ((lane >> 4) << 3) + (lane & 7)) * ROWB + ((lane >> 3) & 1) * 16);

    float acc[2][4][4];
#pragma unroll
    for (int mt = 0; mt < 2; ++mt)
#pragma unroll
        for (int nt = 0; nt < 4; ++nt)
#pragma unroll
            for (int j = 0; j < 4; ++j) acc[mt][nt][j] = 0.0f;

    stage_load(0, 0); CP_COMMIT();

    for (int kt = 0; kt < NT; ++kt) {
        CP_WAIT(0);
        __syncthreads();
        if (kt + 1 < NT) { stage_load((kt + 1) & 1, kt + 1); CP_COMMIT(); }

        const uint32_t st = sbase + (kt & 1) * STAGEB;
#pragma unroll
        for (int s = 0; s < 4; ++s) {          // four k16 steps per BK=64
            uint32_t ah[2][4], al[2][4], bh[4][2], bl[4][2];
#pragma unroll
            for (int mt = 0; mt < 2; ++mt) {
                uint32_t a = st + aOff + mt * 16 * ROWB + s * 32;
                LDSM_X4(ah[mt][0], ah[mt][1], ah[mt][2], ah[mt][3], a);
                LDSM_X4(al[mt][0], al[mt][1], al[mt][2], al[mt][3], a + LO_OFF);
            }
#pragma unroll
            for (int p = 0; p < 2; ++p) {
                uint32_t a = st + bOff + p * 16 * ROWB + s * 32;
                LDSM_X4(bh[2*p][0], bh[2*p][1], bh[2*p+1][0], bh[2*p+1][1], a);
                LDSM_X4(bl[2*p][0], bl[2*p][1], bl[2*p+1][0], bl[2*p+1][1], a + LO_OFF);
            }
#pragma unroll
            for (int mt = 0; mt < 2; ++mt)
#pragma unroll
                for (int nt = 0; nt < 4; ++nt) {
                    mma_bf16(acc[mt][nt], ah[mt], bh[nt][0], bh[nt][1]);
                    mma_bf16(acc[mt][nt], ah[mt], bl[nt][0], bl[nt][1]);
                    mma_bf16(acc[mt][nt], al[mt], bh[nt][0], bh[nt][1]);
                }
        }
        __syncthreads();
    }

    const int r0 = bm + warp_m * 32 + (lane >> 2);
    const int c0 = bn + warp_n * 32 + (lane & 3) * 2;
#pragma unroll
    for (int mt = 0; mt < 2; ++mt) {
#pragma unroll
        for (int nt = 0; nt < 4; ++nt) {
            int col = c0 + nt * 8;
            float bx = bias[col], by = bias[col + 1];
            float vx0 = acc[mt][nt][0] + bx, vy0 = acc[mt][nt][1] + by;
            float vx1 = acc[mt][nt][2] + bx, vy1 = acc[mt][nt][3] + by;
            int ra = r0 + mt * 16, rb = ra + 8;
            if (HILO) {
                uint32_t h0, l0, h1, l1;
                hilo2(vx0, vy0, h0, l0);
                hilo2(vx1, vy1, h1, l1);
                size_t p0 = (size_t)ra * (N >> 1) + (col >> 1);
                size_t p1 = (size_t)rb * (N >> 1) + (col >> 1);
                Ch[p0] = h0; Cl[p0] = l0;
                Ch[p1] = h1; Cl[p1] = l1;
            } else {
                *(float2*)(Cf + (size_t)ra * N + col) = make_float2(vx0, vy0);
                *(float2*)(Cf + (size_t)rb * N + col) = make_float2(vx1, vy1);
            }
        }
    }
}

// ---------------------------------------------------------------------------
// fp32 -> bf16 hi/lo split
// ---------------------------------------------------------------------------
__global__ __launch_bounds__(256) void split_bf16(
    const float4* __restrict__ src, __nv_bfloat162* __restrict__ hi,
    __nv_bfloat162* __restrict__ lo, int n4)
{
    int i = blockIdx.x * blockDim.x + threadIdx.x;
    if (i >= n4) return;
    float4 v = src[i];
    __nv_bfloat16 h0 = __float2bfloat16(v.x);
    __nv_bfloat16 h1 = __float2bfloat16(v.y);
    __nv_bfloat16 h2 = __float2bfloat16(v.z);
    __nv_bfloat16 h3 = __float2bfloat16(v.w);
    __nv_bfloat16 l0 = __float2bfloat16(v.x - __bfloat162float(h0));
    __nv_bfloat16 l1 = __float2bfloat16(v.y - __bfloat162float(h1));
    __nv_bfloat16 l2 = __float2bfloat16(v.z - __bfloat162float(h2));
    __nv_bfloat16 l3 = __float2bfloat16(v.w - __bfloat162float(h3));
    hi[2 * i]     = __halves2bfloat162(h0, h1);
    hi[2 * i + 1] = __halves2bfloat162(h2, h3);
    lo[2 * i]     = __halves2bfloat162(l0, l1);
    lo[2 * i + 1] = __halves2bfloat162(l2, l3);
}

// ---------------------------------------------------------------------------
// Tensor-core sliding-window attention (unchanged from round 4)
// ---------------------------------------------------------------------------
__global__ __launch_bounds__(128, 1) void attn_mma(
    const __nv_bfloat16* __restrict__ qkvh, const __nv_bfloat16* __restrict__ qkvl,
    const int* __restrict__ pmask,
    uint32_t* __restrict__ Oh, uint32_t* __restrict__ Ol)
{
    extern __shared__ char smem[];
    const uint32_t sb = smem_u32(smem);
    const int b = blockIdx.z, h = blockIdx.y, q0 = blockIdx.x * 64;
    const int tid = threadIdx.x, lane = tid & 31, w = tid >> 5;

    for (int i = tid; i < 64 * 8; i += 128) {
        int r = i >> 3, c = i & 7;
        size_t g = (size_t)(b * L_ + q0 + r) * NQKV_ + h * 192 + c * 8;
        *(uint4*)(smem + S_QH + r * AROWB + c * 16) = *(const uint4*)(qkvh + g);
        *(uint4*)(smem + S_QL + r * AROWB + c * 16) = *(const uint4*)(qkvl + g);
    }
    for (int i = tid; i < 128 * 8; i += 128) {
        int r = i >> 3, c = i & 7;
        int pos = q0 - 32 + r;
        uint4 z = make_uint4(0, 0, 0, 0);
        uint4 kh = z, kl = z, vh = z, vl = z;
        if (pos >= 0 && pos < L_) {
            size_t g = (size_t)(b * L_ + pos) * NQKV_ + h * 192 + c * 8;
            kh = *(const uint4*)(qkvh + g + 64);
            kl = *(const uint4*)(qkvl + g + 64);
            vh = *(const uint4*)(qkvh + g + 128);
            vl = *(const uint4*)(qkvl + g + 128);
        }
        *(uint4*)(smem + S_KH + r * AROWB + c * 16) = kh;
        *(uint4*)(smem + S_KL + r * AROWB + c * 16) = kl;
        *(uint4*)(smem + S_VH + r * AROWB + c * 16) = vh;
        *(uint4*)(smem + S_VL + r * AROWB + c * 16) = vl;
    }
    {
        int pos = q0 - 32 + tid;
        int ok = 0;
        if (pos >= 0 && pos < L_) ok = (pmask[b * L_ + pos] != 0);
        ((int*)(smem + S_OK))[tid] = ok;
    }
    __syncthreads();
    const int* okk = (const int*)(smem + S_OK);

    float S[16][4];
#pragma unroll
    for (int i = 0; i < 16; ++i)
#pragma unroll
        for (int j = 0; j < 4; ++j) S[i][j] = 0.0f;

    uint32_t qfh[4][4], qfl[4][4];
    {
        uint32_t aoff = (uint32_t)((w * 16 + (lane & 15)) * AROWB + (lane >> 4) * 16);
#pragma unroll
        for (int ks = 0; ks < 4; ++ks) {
            LDSM_X4(qfh[ks][0], qfh[ks][1], qfh[ks][2], qfh[ks][3], sb + S_QH + aoff + ks * 32);
            LDSM_X4(qfl[ks][0], qfl[ks][1], qfl[ks][2], qfl[ks][3], sb + S_QL + aoff + ks * 32);
        }
    }
    {
        uint32_t boff = (uint32_t)(((((lane >> 4) << 3) + (lane & 7)) * AROWB) + ((lane >> 3) & 1) * 16);
#pragma unroll
        for (int kb = 0; kb < 8; ++kb) {
            uint32_t base = boff + kb * 16 * AROWB;
#pragma unroll
            for (int ks = 0; ks < 4; ++ks) {
                uint32_t bh0, bh1, bh2, bh3, bl0, bl1, bl2, bl3;
                LDSM_X4(bh0, bh1, bh2, bh3, sb + S_KH + base + ks * 32);
                LDSM_X4(bl0, bl1, bl2, bl3, sb + S_KL + base + ks * 32);
                mma_bf16(S[2 * kb],     qfh[ks], bh0, bh1);
                mma_bf16(S[2 * kb],     qfh[ks], bl0, bl1);
                mma_bf16(S[2 * kb],     qfl[ks], bh0, bh1);
                mma_bf16(S[2 * kb + 1], qfh[ks], bh2, bh3);
                mma_bf16(S[2 * kb + 1], qfh[ks], bl2, bl3);
                mma_bf16(S[2 * kb + 1], qfl[ks], bh2, bh3);
            }
        }
    }

    const int rlo = w * 16 + (lane >> 2);
    const int rhi = rlo + 8;
    const float scale = 0.125f;
    const float NEGS = -12500.0f;
    float mlo = -3.0e38f, mhi = -3.0e38f;
#pragma unroll
    for (int nb = 0; nb < 16; ++nb) {
#pragma unroll
        for (int p = 0; p < 2; ++p) {
            int col = nb * 8 + (lane & 3) * 2 + p;
            float s0 = S[nb][p];
            int d0 = col - rlo;
            s0 = (d0 >= 0 && d0 <= 64) ? (okk[col] ? s0 * scale : NEGS) : -3.0e38f;
            S[nb][p] = s0;
            mlo = fmaxf(mlo, s0);
            float s1 = S[nb][2 + p];
            int d1 = col - rhi;
            s1 = (d1 >= 0 && d1 <= 64) ? (okk[col] ? s1 * scale : NEGS) : -3.0e38f;
            S[nb][2 + p] = s1;
            mhi = fmaxf(mhi, s1);
        }
    }
#pragma unroll
    for (int o = 1; o <= 2; o <<= 1) {
        mlo = fmaxf(mlo, __shfl_xor_sync(0xffffffffu, mlo, o));
        mhi = fmaxf(mhi, __shfl_xor_sync(0xffffffffu, mhi, o));
    }
    float slo = 0.f, shi = 0.f;
#pragma unroll
    for (int nb = 0; nb < 16; ++nb) {
#pragma unroll
        for (int p = 0; p < 2; ++p) {
            float e0 = __expf(S[nb][p] - mlo);     S[nb][p] = e0;     slo += e0;
            float e1 = __expf(S[nb][2 + p] - mhi); S[nb][2 + p] = e1; shi += e1;
        }
    }
#pragma unroll
    for (int o = 1; o <= 2; o <<= 1) {
        slo += __shfl_xor_sync(0xffffffffu, slo, o);
        shi += __shfl_xor_sync(0xffffffffu, shi, o);
    }
    const float invlo = 1.0f / slo;
    const float invhi = 1.0f / shi;

    uint32_t ph[8][4], pl[8][4];
#pragma unroll
    for (int kb = 0; kb < 8; ++kb) {
        hilo2(S[2 * kb][0] * invlo,     S[2 * kb][1] * invlo,     ph[kb][0], pl[kb][0]);
        hilo2(S[2 * kb][2] * invhi,     S[2 * kb][3] * invhi,     ph[kb][1], pl[kb][1]);
        hilo2(S[2 * kb + 1][0] * invlo, S[2 * kb + 1][1] * invlo, ph[kb][2], pl[kb][2]);
        hilo2(S[2 * kb + 1][2] * invhi, S[2 * kb + 1][3] * invhi, ph[kb][3], pl[kb][3]);
    }

    float O[8][4];
#pragma unroll
    for (int i = 0; i < 8; ++i)
#pragma unroll
        for (int j = 0; j < 4; ++j) O[i][j] = 0.0f;

    {
        uint32_t voff = (uint32_t)((lane & 15) * AROWB + (lane >> 4) * 16);
#pragma unroll
        for (int kb = 0; kb < 8; ++kb) {
            uint32_t base = voff + kb * 16 * AROWB;
#pragma unroll
            for (int db = 0; db < 4; ++db) {
                uint32_t vh0, vh1, vh2, vh3, vl0, vl1, vl2, vl3;
                LDSM_X4_T(vh0, vh1, vh2, vh3, sb + S_VH + base + db * 32);
                LDSM_X4_T(vl0, vl1, vl2, vl3, sb + S_VL + base + db * 32);
                mma_bf16(O[2 * db],     ph[kb], vh0, vh1);
                mma_bf16(O[2 * db],     ph[kb], vl0, vl1);
                mma_bf16(O[2 * db],     pl[kb], vh0, vh1);
                mma_bf16(O[2 * db + 1], ph[kb], vh2, vh3);
                mma_bf16(O[2 * db + 1], ph[kb], vl2, vl3);
                mma_bf16(O[2 * db + 1], pl[kb], vh2, vh3);
            }
        }
    }

    const size_t rowlo = (size_t)(b * L_ + q0 + rlo);
    const size_t rowhi = rowlo + 8;
#pragma unroll
    for (int nb = 0; nb < 8; ++nb) {
        int col = h * 64 + nb * 8 + (lane & 3) * 2;
        uint32_t h0, l0, h1, l1;
        hilo2(O[nb][0], O[nb][1], h0, l0);
        hilo2(O[nb][2], O[nb][3], h1, l1);
        Oh[rowlo * (E_ / 2) + (col >> 1)] = h0;
        Ol[rowlo * (E_ / 2) + (col >> 1)] = l0;
        Oh[rowhi * (E_ / 2) + (col >> 1)] = h1;
        Ol[rowhi * (E_ / 2) + (col >> 1)] = l1;
    }
}

// ---------------------------------------------------------------------------
// kernel_launch
// ---------------------------------------------------------------------------
extern "C" void kernel_launch(void* const* d_in, const int* in_sizes, int n_in,
                              void* d_out, int out_size)
{
    const float* x      = (const float*)d_in[0];
    const int*   pmask  = (const int*)d_in[1];
    const float* W_qkv  = (const float*)d_in[2];
    const float* b_qkv  = (const float*)d_in[3];
    const float* W_o    = (const float*)d_in[4];
    const float* b_o    = (const float*)d_in[5];
    float* out = (float*)d_out;

    __nv_bfloat16 *qkvh, *qkvl, *xh, *xl, *oh, *ol, *wqh, *wql, *woh, *wol;
    cudaGetSymbolAddress((void**)&qkvh, g_qkvh);
    cudaGetSymbolAddress((void**)&qkvl, g_qkvl);
    cudaGetSymbolAddress((void**)&xh, g_xh);
    cudaGetSymbolAddress((void**)&xl, g_xl);
    cudaGetSymbolAddress((void**)&oh, g_oh);
    cudaGetSymbolAddress((void**)&ol, g_ol);
    cudaGetSymbolAddress((void**)&wqh, g_wqh);
    cudaGetSymbolAddress((void**)&wql, g_wql);
    cudaGetSymbolAddress((void**)&woh, g_woh);
    cudaGetSymbolAddress((void**)&wol, g_wol);

    static bool attr_done = false;
    if (!attr_done) {
        cudaFuncSetAttribute(gemm_mma<false>, cudaFuncAttributeMaxDynamicSharedMemorySize, GEMM_SMEM);
        cudaFuncSetAttribute(gemm_mma<true>,  cudaFuncAttributeMaxDynamicSharedMemorySize, GEMM_SMEM);
        cudaFuncSetAttribute(attn_mma, cudaFuncAttributeMaxDynamicSharedMemorySize, ATTN_SMEM);
        attr_done = true;
    }

    {
        int n4 = (ML_ * KD_) / 4;
        split_bf16<<<(n4 + 255) / 256, 256>>>((const float4*)x,
            (__nv_bfloat162*)xh, (__nv_bfloat162*)xl, n4);
        int w4 = (NQKV_ * KD_) / 4;
        split_bf16<<<(w4 + 255) / 256, 256>>>((const float4*)W_qkv,
            (__nv_bfloat162*)wqh, (__nv_bfloat162*)wql, w4);
        int o4 = (E_ * E_) / 4;
        split_bf16<<<(o4 + 255) / 256, 256>>>((const float4*)W_o,
            (__nv_bfloat162*)woh, (__nv_bfloat162*)wol, o4);
    }
    gemm_mma<true><<<dim3(NQKV_ / BN, ML_ / BM), GEMM_THREADS, GEMM_SMEM>>>(
        xh, xl, wqh, wql, b_qkv, nullptr,
        (uint32_t*)qkvh, (uint32_t*)qkvl, ML_, NQKV_, KD_);
    attn_mma<<<dim3(L_ / 64, H_, B_), 128, ATTN_SMEM>>>(
        qkvh, qkvl, pmask, (uint32_t*)oh, (uint32_t*)ol);
    gemm_mma<false><<<dim3(E_ / BN, ML_ / BM), GEMM_THREADS, GEMM_SMEM>>>(
        oh, ol, woh, wol, b_o, out, nullptr, nullptr, ML_, E_, KD_);
}